// round 8
// baseline (speedup 1.0000x reference)
#include <cuda_runtime.h>
#include <math.h>
#include <stdint.h>

#define D_MODEL 2048
#define NEXP    128
#define BM      64
#define KC      32
#define NKC     (D_MODEL / KC)    // 64
#define NTHREADS 256
#define TOPK    8

#define SAW    36                  // smem row stride in floats (conflict-free)
#define ATF    (64 * SAW)          // A tile floats (2304)
#define BTF    (128 * SAW)         // B tile floats (4608)
#define BUFF   (2 * ATF + 2 * BTF) // floats per buffer: A_hi, A_lo, B_hi, B_lo (13824)
#define SMEM_REQ (2 * BUFF * 4)    // 110592 bytes -> 2 CTAs/SM
#define LS_W   132

__device__ __forceinline__ float tf32_rna(float x) {
    uint32_t u;
    asm("cvt.rna.tf32.f32 %0, %1;" : "=r"(u) : "f"(x));
    return __uint_as_float(u);
}
__device__ __forceinline__ void split(float x, float& h, float& l) {
    h = tf32_rna(x);
    l = tf32_rna(x - h);
}

__device__ __forceinline__ void mma_tf32(float* d, const float* a, float b0, float b1) {
    asm volatile(
        "mma.sync.aligned.m16n8k8.row.col.f32.tf32.tf32.f32 "
        "{%0,%1,%2,%3}, {%4,%5,%6,%7}, {%8,%9}, {%0,%1,%2,%3};"
        : "+f"(d[0]), "+f"(d[1]), "+f"(d[2]), "+f"(d[3])
        : "r"(__float_as_uint(a[0])), "r"(__float_as_uint(a[1])),
          "r"(__float_as_uint(a[2])), "r"(__float_as_uint(a[3])),
          "r"(__float_as_uint(b0)), "r"(__float_as_uint(b1)));
}

__global__ __launch_bounds__(NTHREADS, 2)
void moe_router_kernel(const float* __restrict__ X,
                       const float* __restrict__ W,
                       const float* __restrict__ BIAS,
                       float* __restrict__ OUTW,
                       float* __restrict__ OUTI,
                       int writeIdx, int Ntok)
{
    extern __shared__ float Sm[];

    const int tid  = threadIdx.x;
    const int wid  = tid >> 5;
    const int lane = tid & 31;
    const int bm0  = blockIdx.x * BM;

    const int wm = wid >> 2;        // 0..1 -> token base wm*32
    const int wn = wid & 3;         // 0..3 -> expert base wn*32

    // A loads: 512 float4/chunk, 2/thread;  B loads: 1024 float4/chunk, 4/thread
    int rA[2], cA[2], rB[4], cB[4];
#pragma unroll
    for (int p = 0; p < 2; ++p) {
        int idx = tid + p * NTHREADS;
        rA[p] = idx >> 3;
        cA[p] = (idx & 7) * 4;
    }
#pragma unroll
    for (int p = 0; p < 4; ++p) {
        int idx = tid + p * NTHREADS;
        rB[p] = idx >> 3;
        cB[p] = (idx & 7) * 4;
    }

    float acc[2][4][4];
#pragma unroll
    for (int i = 0; i < 2; ++i)
#pragma unroll
        for (int j = 0; j < 4; ++j)
#pragma unroll
            for (int q = 0; q < 4; ++q)
                acc[i][j][q] = 0.f;

    float4 axr[2], bwr[4];
#pragma unroll
    for (int p = 0; p < 2; ++p) {
        int row = bm0 + rA[p];
        axr[p] = (row < Ntok)
            ? *reinterpret_cast<const float4*>(X + (size_t)row * D_MODEL + cA[p])
            : make_float4(0.f, 0.f, 0.f, 0.f);
    }
#pragma unroll
    for (int p = 0; p < 4; ++p)
        bwr[p] = *reinterpret_cast<const float4*>(W + (size_t)rB[p] * D_MODEL + cB[p]);

    // store chunk 0 into buf 0
    {
        float* AH = Sm;
        float* AL = Sm + ATF;
        float* BH = Sm + 2 * ATF;
        float* BL = Sm + 2 * ATF + BTF;
#pragma unroll
        for (int p = 0; p < 2; ++p) {
            int off = rA[p] * SAW + cA[p];
            float4 h4, l4;
            split(axr[p].x, h4.x, l4.x); split(axr[p].y, h4.y, l4.y);
            split(axr[p].z, h4.z, l4.z); split(axr[p].w, h4.w, l4.w);
            *reinterpret_cast<float4*>(AH + off) = h4;
            *reinterpret_cast<float4*>(AL + off) = l4;
        }
#pragma unroll
        for (int p = 0; p < 4; ++p) {
            int off = rB[p] * SAW + cB[p];
            float4 h4, l4;
            split(bwr[p].x, h4.x, l4.x); split(bwr[p].y, h4.y, l4.y);
            split(bwr[p].z, h4.z, l4.z); split(bwr[p].w, h4.w, l4.w);
            *reinterpret_cast<float4*>(BH + off) = h4;
            *reinterpret_cast<float4*>(BL + off) = l4;
        }
    }
    __syncthreads();

    const int alanebase = (wm * 32 + (lane >> 2)) * SAW + (lane & 3);
    const int blanebase = (wn * 32 + (lane >> 2)) * SAW + (lane & 3);

    for (int c = 0; c < NKC; ++c) {
        const int buf = c & 1;
        if (c + 1 < NKC) {
            const int k0 = (c + 1) * KC;
#pragma unroll
            for (int p = 0; p < 2; ++p) {
                int row = bm0 + rA[p];
                axr[p] = (row < Ntok)
                    ? *reinterpret_cast<const float4*>(X + (size_t)row * D_MODEL + k0 + cA[p])
                    : make_float4(0.f, 0.f, 0.f, 0.f);
            }
#pragma unroll
            for (int p = 0; p < 4; ++p)
                bwr[p] = *reinterpret_cast<const float4*>(W + (size_t)rB[p] * D_MODEL + k0 + cB[p]);
        }

        const float* sb = Sm + buf * BUFF;
        const float* AH = sb;
        const float* AL = sb + ATF;
        const float* BH = sb + 2 * ATF;
        const float* BL = sb + 2 * ATF + BTF;
#pragma unroll
        for (int ks = 0; ks < KC / 8; ++ks) {
            const int kb = ks * 8;
            float aH[2][4], aL[2][4];
#pragma unroll
            for (int mt = 0; mt < 2; ++mt) {
                int b0 = alanebase + mt * 16 * SAW + kb;
                aH[mt][0] = AH[b0];
                aH[mt][1] = AH[b0 + 8 * SAW];
                aH[mt][2] = AH[b0 + 4];
                aH[mt][3] = AH[b0 + 8 * SAW + 4];
                aL[mt][0] = AL[b0];
                aL[mt][1] = AL[b0 + 8 * SAW];
                aL[mt][2] = AL[b0 + 4];
                aL[mt][3] = AL[b0 + 8 * SAW + 4];
            }
#pragma unroll
            for (int ng = 0; ng < 4; ++ng) {
                int bb = blanebase + ng * 8 * SAW + kb;
                float bh0 = BH[bb], bh1 = BH[bb + 4];
                float bl0 = BL[bb], bl1 = BL[bb + 4];
#pragma unroll
                for (int mt = 0; mt < 2; ++mt) {
                    mma_tf32(acc[mt][ng], aL[mt], bh0, bh1);   // lo*hi
                    mma_tf32(acc[mt][ng], aH[mt], bl0, bl1);   // hi*lo
                    mma_tf32(acc[mt][ng], aH[mt], bh0, bh1);   // hi*hi
                }
            }
        }

        if (c + 1 < NKC) {
            float* db = Sm + ((c + 1) & 1) * BUFF;
            float* nAH = db;
            float* nAL = db + ATF;
            float* nBH = db + 2 * ATF;
            float* nBL = db + 2 * ATF + BTF;
            __syncthreads();
#pragma unroll
            for (int p = 0; p < 2; ++p) {
                int off = rA[p] * SAW + cA[p];
                float4 h4, l4;
                split(axr[p].x, h4.x, l4.x); split(axr[p].y, h4.y, l4.y);
                split(axr[p].z, h4.z, l4.z); split(axr[p].w, h4.w, l4.w);
                *reinterpret_cast<float4*>(nAH + off) = h4;
                *reinterpret_cast<float4*>(nAL + off) = l4;
            }
#pragma unroll
            for (int p = 0; p < 4; ++p) {
                int off = rB[p] * SAW + cB[p];
                float4 h4, l4;
                split(bwr[p].x, h4.x, l4.x); split(bwr[p].y, h4.y, l4.y);
                split(bwr[p].z, h4.z, l4.z); split(bwr[p].w, h4.w, l4.w);
                *reinterpret_cast<float4*>(nBH + off) = h4;
                *reinterpret_cast<float4*>(nBL + off) = l4;
            }
            __syncthreads();
        }
    }

    // ---- logits to smem ----
    __syncthreads();
    float* Ls = Sm;
    {
        const int g  = lane >> 2;
        const int t2 = (lane & 3) * 2;
#pragma unroll
        for (int mt = 0; mt < 2; ++mt) {
            int row = wm * 32 + mt * 16 + g;
#pragma unroll
            for (int ng = 0; ng < 4; ++ng) {
                int col = wn * 32 + ng * 8 + t2;
                *reinterpret_cast<float2*>(&Ls[row * LS_W + col]) =
                    make_float2(acc[mt][ng][0], acc[mt][ng][1]);
                *reinterpret_cast<float2*>(&Ls[(row + 8) * LS_W + col]) =
                    make_float2(acc[mt][ng][2], acc[mt][ng][3]);
            }
        }
    }
    __syncthreads();

    // ---- router epilogue: 1 warp per token ----
    for (int t = wid; t < BM; t += (NTHREADS / 32)) {
        int gt = bm0 + t;
        if (gt >= Ntok) continue;
        const float* Lr = Ls + t * LS_W;

        float v0 = Lr[lane];
        float v1 = Lr[lane + 32];
        float v2 = Lr[lane + 64];
        float v3 = Lr[lane + 96];

        float mx = fmaxf(fmaxf(v0, v1), fmaxf(v2, v3));
#pragma unroll
        for (int off = 16; off > 0; off >>= 1)
            mx = fmaxf(mx, __shfl_xor_sync(0xffffffffu, mx, off));

        float e0 = expf(v0 - mx);
        float e1 = expf(v1 - mx);
        float e2 = expf(v2 - mx);
        float e3 = expf(v3 - mx);
        float sum = e0 + e1 + e2 + e3;
#pragma unroll
        for (int off = 16; off > 0; off >>= 1)
            sum += __shfl_xor_sync(0xffffffffu, sum, off);

        float s0 = e0 / sum, s1 = e1 / sum, s2 = e2 / sum, s3 = e3 / sum;

        float bb0 = s0 + __ldg(BIAS + lane);
        float bb1 = s1 + __ldg(BIAS + lane + 32);
        float bb2 = s2 + __ldg(BIAS + lane + 64);
        float bb3 = s3 + __ldg(BIAS + lane + 96);

        float topw[TOPK];
        int   topi[TOPK];
#pragma unroll
        for (int i = 0; i < TOPK; ++i) {
            float bv = bb0; int bi = lane;
            if (bb1 > bv) { bv = bb1; bi = lane + 32; }
            if (bb2 > bv) { bv = bb2; bi = lane + 64; }
            if (bb3 > bv) { bv = bb3; bi = lane + 96; }
#pragma unroll
            for (int off = 16; off > 0; off >>= 1) {
                float ov = __shfl_xor_sync(0xffffffffu, bv, off);
                int   oi = __shfl_xor_sync(0xffffffffu, bi, off);
                if (ov > bv || (ov == bv && oi < bi)) { bv = ov; bi = oi; }
            }
            topi[i] = bi;
            int src = bi & 31, slot = bi >> 5;
            float sv = (slot == 0) ? s0 : (slot == 1) ? s1 : (slot == 2) ? s2 : s3;
            sv = __shfl_sync(0xffffffffu, sv, src);
            topw[i] = sv;
            if (lane == src) {
                if      (slot == 0) bb0 = -INFINITY;
                else if (slot == 1) bb1 = -INFINITY;
                else if (slot == 2) bb2 = -INFINITY;
                else                bb3 = -INFINITY;
            }
        }

        float n2 = 0.f;
#pragma unroll
        for (int i = 0; i < TOPK; ++i) n2 += topw[i] * topw[i];
        float nrm = sqrtf(n2);

        if (lane == 0) {
            size_t base = (size_t)gt * TOPK;
            float4 w0 = make_float4(topw[0] / nrm, topw[1] / nrm, topw[2] / nrm, topw[3] / nrm);
            float4 w1 = make_float4(topw[4] / nrm, topw[5] / nrm, topw[6] / nrm, topw[7] / nrm);
            *reinterpret_cast<float4*>(&OUTW[base])     = w0;
            *reinterpret_cast<float4*>(&OUTW[base + 4]) = w1;
            if (writeIdx) {
                float4 i0 = make_float4((float)topi[0], (float)topi[1], (float)topi[2], (float)topi[3]);
                float4 i1 = make_float4((float)topi[4], (float)topi[5], (float)topi[6], (float)topi[7]);
                *reinterpret_cast<float4*>(&OUTI[base])     = i0;
                *reinterpret_cast<float4*>(&OUTI[base + 4]) = i1;
            }
        }
    }
}

extern "C" void kernel_launch(void* const* d_in, const int* in_sizes, int n_in,
                              void* d_out, int out_size)
{
    const float* x    = (const float*)d_in[0];
    const float* w    = (const float*)d_in[1];
    const float* bias = (const float*)d_in[2];

    const int Ntok = in_sizes[0] / D_MODEL;

    float* outw = (float*)d_out;
    int writeIdx = (out_size >= 2 * Ntok * TOPK) ? 1 : 0;
    float* outi = outw + (size_t)Ntok * TOPK;

    cudaFuncSetAttribute(moe_router_kernel,
                         cudaFuncAttributeMaxDynamicSharedMemorySize, SMEM_REQ);

    int grid = (Ntok + BM - 1) / BM;
    moe_router_kernel<<<grid, NTHREADS, SMEM_REQ>>>(x, w, bias, outw, outi, writeIdx, Ntok);
}

// round 9
// speedup vs baseline: 1.0762x; 1.0762x over previous
#include <cuda_runtime.h>
#include <math.h>
#include <stdint.h>

#define D_MODEL 2048
#define NEXP    128
#define BM      128
#define KC      32
#define NKC     (D_MODEL / KC)    // 64
#define NTHREADS 512
#define TOPK    8

#define SAW    36                  // smem row stride in floats (conflict-free)
#define TILEF  (128 * SAW)
#define BUFF   (4 * TILEF)         // A_hi, A_lo, B_hi, B_lo
#define SMEM_REQ (2 * BUFF * 4)    // 147456 bytes
#define LS_W   132

__device__ __forceinline__ float tf32_rna(float x) {
    uint32_t u;
    asm("cvt.rna.tf32.f32 %0, %1;" : "=r"(u) : "f"(x));
    return __uint_as_float(u);
}
__device__ __forceinline__ void split(float x, float& h, float& l) {
    h = tf32_rna(x);
    l = tf32_rna(x - h);
}

__device__ __forceinline__ void mma_tf32(float* d, const float* a, float b0, float b1) {
    asm volatile(
        "mma.sync.aligned.m16n8k8.row.col.f32.tf32.tf32.f32 "
        "{%0,%1,%2,%3}, {%4,%5,%6,%7}, {%8,%9}, {%0,%1,%2,%3};"
        : "+f"(d[0]), "+f"(d[1]), "+f"(d[2]), "+f"(d[3])
        : "r"(__float_as_uint(a[0])), "r"(__float_as_uint(a[1])),
          "r"(__float_as_uint(a[2])), "r"(__float_as_uint(a[3])),
          "r"(__float_as_uint(b0)), "r"(__float_as_uint(b1)));
}

__global__ __launch_bounds__(NTHREADS, 1)
void moe_router_kernel(const float* __restrict__ X,
                       const float* __restrict__ W,
                       const float* __restrict__ BIAS,
                       float* __restrict__ OUTW,
                       float* __restrict__ OUTI,
                       int writeIdx, int Ntok)
{
    extern __shared__ float Sm[];

    const int tid  = threadIdx.x;
    const int wid  = tid >> 5;
    const int lane = tid & 31;
    const int bm0  = blockIdx.x * BM;

    const int wm = wid >> 2;        // 0..3 -> token base wm*32
    const int wn = wid & 3;         // 0..3 -> expert base wn*32

    int rA[2], cA[2];
#pragma unroll
    for (int p = 0; p < 2; ++p) {
        int idx = tid + p * NTHREADS;
        rA[p] = idx >> 3;
        cA[p] = (idx & 7) * 4;
    }

    float acc[2][4][4];
#pragma unroll
    for (int i = 0; i < 2; ++i)
#pragma unroll
        for (int j = 0; j < 4; ++j)
#pragma unroll
            for (int q = 0; q < 4; ++q)
                acc[i][j][q] = 0.f;

    float4 axr[2], bwr[2];
#pragma unroll
    for (int p = 0; p < 2; ++p) {
        int row = bm0 + rA[p];
        axr[p] = (row < Ntok)
            ? *reinterpret_cast<const float4*>(X + (size_t)row * D_MODEL + cA[p])
            : make_float4(0.f, 0.f, 0.f, 0.f);
        bwr[p] = *reinterpret_cast<const float4*>(W + (size_t)rA[p] * D_MODEL + cA[p]);
    }

    {
        float* AH = Sm;
        float* AL = Sm + TILEF;
        float* BH = Sm + 2 * TILEF;
        float* BL = Sm + 3 * TILEF;
#pragma unroll
        for (int p = 0; p < 2; ++p) {
            int off = rA[p] * SAW + cA[p];
            float4 h4, l4;
            split(axr[p].x, h4.x, l4.x); split(axr[p].y, h4.y, l4.y);
            split(axr[p].z, h4.z, l4.z); split(axr[p].w, h4.w, l4.w);
            *reinterpret_cast<float4*>(AH + off) = h4;
            *reinterpret_cast<float4*>(AL + off) = l4;
            split(bwr[p].x, h4.x, l4.x); split(bwr[p].y, h4.y, l4.y);
            split(bwr[p].z, h4.z, l4.z); split(bwr[p].w, h4.w, l4.w);
            *reinterpret_cast<float4*>(BH + off) = h4;
            *reinterpret_cast<float4*>(BL + off) = l4;
        }
    }
    __syncthreads();

    const int alanebase = (wm * 32 + (lane >> 2)) * SAW + (lane & 3);
    const int blanebase = (wn * 32 + (lane >> 2)) * SAW + (lane & 3);

    for (int c = 0; c < NKC; ++c) {
        const int buf = c & 1;
        if (c + 1 < NKC) {
            const int k0 = (c + 1) * KC;
#pragma unroll
            for (int p = 0; p < 2; ++p) {
                int row = bm0 + rA[p];
                axr[p] = (row < Ntok)
                    ? *reinterpret_cast<const float4*>(X + (size_t)row * D_MODEL + k0 + cA[p])
                    : make_float4(0.f, 0.f, 0.f, 0.f);
                bwr[p] = *reinterpret_cast<const float4*>(W + (size_t)rA[p] * D_MODEL + k0 + cA[p]);
            }
        }

        const float* sb = Sm + buf * BUFF;
        const float* AHp = sb + alanebase;
        const float* ALp = sb + TILEF + alanebase;
        const float* BHp = sb + 2 * TILEF + blanebase;
        const float* BLp = sb + 3 * TILEF + blanebase;
#pragma unroll
        for (int ks = 0; ks < KC / 8; ++ks) {
            const int kb = ks * 8;
            // ---- front-batch all fragment loads (32 LDS, max MLP) ----
            float aH[2][4], aL[2][4];
            float bh[4][2], bl[4][2];
#pragma unroll
            for (int mt = 0; mt < 2; ++mt) {
                int b0 = mt * 16 * SAW + kb;
                aH[mt][0] = AHp[b0];
                aH[mt][1] = AHp[b0 + 8 * SAW];
                aH[mt][2] = AHp[b0 + 4];
                aH[mt][3] = AHp[b0 + 8 * SAW + 4];
                aL[mt][0] = ALp[b0];
                aL[mt][1] = ALp[b0 + 8 * SAW];
                aL[mt][2] = ALp[b0 + 4];
                aL[mt][3] = ALp[b0 + 8 * SAW + 4];
            }
#pragma unroll
            for (int ng = 0; ng < 4; ++ng) {
                int bb = ng * 8 * SAW + kb;
                bh[ng][0] = BHp[bb];
                bh[ng][1] = BHp[bb + 4];
                bl[ng][0] = BLp[bb];
                bl[ng][1] = BLp[bb + 4];
            }
            // ---- term-major MMA issue: 8 independent accs per term ----
#pragma unroll
            for (int ng = 0; ng < 4; ++ng)
#pragma unroll
                for (int mt = 0; mt < 2; ++mt)
                    mma_tf32(acc[mt][ng], aH[mt], bh[ng][0], bh[ng][1]);   // hi*hi
#pragma unroll
            for (int ng = 0; ng < 4; ++ng)
#pragma unroll
                for (int mt = 0; mt < 2; ++mt)
                    mma_tf32(acc[mt][ng], aH[mt], bl[ng][0], bl[ng][1]);   // hi*lo
#pragma unroll
            for (int ng = 0; ng < 4; ++ng)
#pragma unroll
                for (int mt = 0; mt < 2; ++mt)
                    mma_tf32(acc[mt][ng], aL[mt], bh[ng][0], bh[ng][1]);   // lo*hi
        }

        if (c + 1 < NKC) {
            float* db = Sm + ((c + 1) & 1) * BUFF;
            float* nAH = db;
            float* nAL = db + TILEF;
            float* nBH = db + 2 * TILEF;
            float* nBL = db + 3 * TILEF;
            __syncthreads();
#pragma unroll
            for (int p = 0; p < 2; ++p) {
                int off = rA[p] * SAW + cA[p];
                float4 h4, l4;
                split(axr[p].x, h4.x, l4.x); split(axr[p].y, h4.y, l4.y);
                split(axr[p].z, h4.z, l4.z); split(axr[p].w, h4.w, l4.w);
                *reinterpret_cast<float4*>(nAH + off) = h4;
                *reinterpret_cast<float4*>(nAL + off) = l4;
                split(bwr[p].x, h4.x, l4.x); split(bwr[p].y, h4.y, l4.y);
                split(bwr[p].z, h4.z, l4.z); split(bwr[p].w, h4.w, l4.w);
                *reinterpret_cast<float4*>(nBH + off) = h4;
                *reinterpret_cast<float4*>(nBL + off) = l4;
            }
            __syncthreads();
        }
    }

    // ---- logits to smem ----
    __syncthreads();
    float* Ls = Sm;
    {
        const int g  = lane >> 2;
        const int t2 = (lane & 3) * 2;
#pragma unroll
        for (int mt = 0; mt < 2; ++mt) {
            int row = wm * 32 + mt * 16 + g;
#pragma unroll
            for (int ng = 0; ng < 4; ++ng) {
                int col = wn * 32 + ng * 8 + t2;
                *reinterpret_cast<float2*>(&Ls[row * LS_W + col]) =
                    make_float2(acc[mt][ng][0], acc[mt][ng][1]);
                *reinterpret_cast<float2*>(&Ls[(row + 8) * LS_W + col]) =
                    make_float2(acc[mt][ng][2], acc[mt][ng][3]);
            }
        }
    }
    __syncthreads();

    // ---- router epilogue: 1 warp per token ----
    for (int t = wid; t < BM; t += (NTHREADS / 32)) {
        int gt = bm0 + t;
        if (gt >= Ntok) continue;
        const float* Lr = Ls + t * LS_W;

        float v0 = Lr[lane];
        float v1 = Lr[lane + 32];
        float v2 = Lr[lane + 64];
        float v3 = Lr[lane + 96];

        float mx = fmaxf(fmaxf(v0, v1), fmaxf(v2, v3));
#pragma unroll
        for (int off = 16; off > 0; off >>= 1)
            mx = fmaxf(mx, __shfl_xor_sync(0xffffffffu, mx, off));

        float e0 = expf(v0 - mx);
        float e1 = expf(v1 - mx);
        float e2 = expf(v2 - mx);
        float e3 = expf(v3 - mx);
        float sum = e0 + e1 + e2 + e3;
#pragma unroll
        for (int off = 16; off > 0; off >>= 1)
            sum += __shfl_xor_sync(0xffffffffu, sum, off);

        float s0 = e0 / sum, s1 = e1 / sum, s2 = e2 / sum, s3 = e3 / sum;

        float bb0 = s0 + __ldg(BIAS + lane);
        float bb1 = s1 + __ldg(BIAS + lane + 32);
        float bb2 = s2 + __ldg(BIAS + lane + 64);
        float bb3 = s3 + __ldg(BIAS + lane + 96);

        float topw[TOPK];
        int   topi[TOPK];
#pragma unroll
        for (int i = 0; i < TOPK; ++i) {
            float bv = bb0; int bi = lane;
            if (bb1 > bv) { bv = bb1; bi = lane + 32; }
            if (bb2 > bv) { bv = bb2; bi = lane + 64; }
            if (bb3 > bv) { bv = bb3; bi = lane + 96; }
#pragma unroll
            for (int off = 16; off > 0; off >>= 1) {
                float ov = __shfl_xor_sync(0xffffffffu, bv, off);
                int   oi = __shfl_xor_sync(0xffffffffu, bi, off);
                if (ov > bv || (ov == bv && oi < bi)) { bv = ov; bi = oi; }
            }
            topi[i] = bi;
            int src = bi & 31, slot = bi >> 5;
            float sv = (slot == 0) ? s0 : (slot == 1) ? s1 : (slot == 2) ? s2 : s3;
            sv = __shfl_sync(0xffffffffu, sv, src);
            topw[i] = sv;
            if (lane == src) {
                if      (slot == 0) bb0 = -INFINITY;
                else if (slot == 1) bb1 = -INFINITY;
                else if (slot == 2) bb2 = -INFINITY;
                else                bb3 = -INFINITY;
            }
        }

        float n2 = 0.f;
#pragma unroll
        for (int i = 0; i < TOPK; ++i) n2 += topw[i] * topw[i];
        float nrm = sqrtf(n2);

        if (lane == 0) {
            size_t base = (size_t)gt * TOPK;
            float4 w0 = make_float4(topw[0] / nrm, topw[1] / nrm, topw[2] / nrm, topw[3] / nrm);
            float4 w1 = make_float4(topw[4] / nrm, topw[5] / nrm, topw[6] / nrm, topw[7] / nrm);
            *reinterpret_cast<float4*>(&OUTW[base])     = w0;
            *reinterpret_cast<float4*>(&OUTW[base + 4]) = w1;
            if (writeIdx) {
                float4 i0 = make_float4((float)topi[0], (float)topi[1], (float)topi[2], (float)topi[3]);
                float4 i1 = make_float4((float)topi[4], (float)topi[5], (float)topi[6], (float)topi[7]);
                *reinterpret_cast<float4*>(&OUTI[base])     = i0;
                *reinterpret_cast<float4*>(&OUTI[base + 4]) = i1;
            }
        }
    }
}

extern "C" void kernel_launch(void* const* d_in, const int* in_sizes, int n_in,
                              void* d_out, int out_size)
{
    const float* x    = (const float*)d_in[0];
    const float* w    = (const float*)d_in[1];
    const float* bias = (const float*)d_in[2];

    const int Ntok = in_sizes[0] / D_MODEL;

    float* outw = (float*)d_out;
    int writeIdx = (out_size >= 2 * Ntok * TOPK) ? 1 : 0;
    float* outi = outw + (size_t)Ntok * TOPK;

    cudaFuncSetAttribute(moe_router_kernel,
                         cudaFuncAttributeMaxDynamicSharedMemorySize, SMEM_REQ);

    int grid = (Ntok + BM - 1) / BM;
    moe_router_kernel<<<grid, NTHREADS, SMEM_REQ>>>(x, w, bias, outw, outi, writeIdx, Ntok);
}

// round 10
// speedup vs baseline: 1.7486x; 1.6249x over previous
#include <cuda_runtime.h>
#include <cuda_fp16.h>
#include <math.h>
#include <stdint.h>

#define D_MODEL 2048
#define NEXP    128
#define BM      128
#define KC      32
#define NKC     (D_MODEL / KC)    // 64
#define NTHREADS 512
#define TOPK    8

#define SAW    40                   // smem stride in halves (validated conflict shape in R5)
#define TILEH  (128 * SAW)          // halves per tile
#define TILEB  (TILEH * 2)          // 10240 bytes
#define BUFB   (4 * TILEB)          // A_hi, A_lo, B_hi, B_lo = 40960 B
#define SMEM_REQ (2 * BUFB)         // 81920 B
#define LS_W   132

#define SX 64.0f
#define SW 256.0f
#define DESCALE 6.103515625e-05f    // 2^-14, exact

__device__ __forceinline__ uint32_t smem_u32(const void* p) {
    uint32_t a;
    asm("{ .reg .u64 t; cvta.to.shared.u64 t, %1; cvt.u32.u64 %0, t; }" : "=r"(a) : "l"(p));
    return a;
}

__device__ __forceinline__ void ldmx4(uint32_t& r0, uint32_t& r1, uint32_t& r2, uint32_t& r3,
                                      uint32_t addr) {
    asm volatile("ldmatrix.sync.aligned.m8n8.x4.shared.b16 {%0,%1,%2,%3}, [%4];"
                 : "=r"(r0), "=r"(r1), "=r"(r2), "=r"(r3) : "r"(addr));
}

__device__ __forceinline__ void mma16816(float* d, const uint32_t* a, uint32_t b0, uint32_t b1) {
    asm volatile(
        "mma.sync.aligned.m16n8k16.row.col.f32.f16.f16.f32 "
        "{%0,%1,%2,%3}, {%4,%5,%6,%7}, {%8,%9}, {%0,%1,%2,%3};"
        : "+f"(d[0]), "+f"(d[1]), "+f"(d[2]), "+f"(d[3])
        : "r"(a[0]), "r"(a[1]), "r"(a[2]), "r"(a[3]), "r"(b0), "r"(b1));
}

// scale + split float4 into hi/lo half2-pairs (4 halves -> uint2 each)
__device__ __forceinline__ void split4(float4 v, float s, uint2& hi, uint2& lo) {
    float a = v.x * s, b = v.y * s, c = v.z * s, d = v.w * s;
    __half2 h01 = __floats2half2_rn(a, b);
    __half2 h23 = __floats2half2_rn(c, d);
    float2 f01 = __half22float2(h01);
    float2 f23 = __half22float2(h23);
    __half2 l01 = __floats2half2_rn(a - f01.x, b - f01.y);
    __half2 l23 = __floats2half2_rn(c - f23.x, d - f23.y);
    hi.x = *reinterpret_cast<uint32_t*>(&h01);
    hi.y = *reinterpret_cast<uint32_t*>(&h23);
    lo.x = *reinterpret_cast<uint32_t*>(&l01);
    lo.y = *reinterpret_cast<uint32_t*>(&l23);
}

__global__ __launch_bounds__(NTHREADS, 1)
void moe_router_kernel(const float* __restrict__ X,
                       const float* __restrict__ W,
                       const float* __restrict__ BIAS,
                       float* __restrict__ OUTW,
                       float* __restrict__ OUTI,
                       int writeIdx, int Ntok)
{
    extern __shared__ char sraw[];
    const uint32_t sbase = smem_u32(sraw);

    const int tid  = threadIdx.x;
    const int wid  = tid >> 5;
    const int lane = tid & 31;
    const int bm0  = blockIdx.x * BM;

    const int wm = wid >> 2;        // 0..3 -> token base wm*32
    const int wn = wid & 3;         // 0..3 -> expert base wn*32

    // ldmatrix per-lane offsets (bytes) — validated in R5
    const uint32_t aoff = (uint32_t)(((lane & 15) * SAW + (lane >> 4) * 8) * 2);
    const uint32_t boff = (uint32_t)((((lane & 7) + ((lane >> 4) << 3)) * SAW) * 2
                                     + ((lane >> 3) & 1) * 16);

    // staging: per operand per chunk 1024 float4; 2 per thread
    int rA[2], cA[2];
#pragma unroll
    for (int p = 0; p < 2; ++p) {
        int idx = tid + p * NTHREADS;
        rA[p] = idx >> 3;
        cA[p] = (idx & 7) * 4;
    }

    float acc[2][4][4];
#pragma unroll
    for (int i = 0; i < 2; ++i)
#pragma unroll
        for (int j = 0; j < 4; ++j)
#pragma unroll
            for (int q = 0; q < 4; ++q)
                acc[i][j][q] = 0.f;

    float4 axr[2], bwr[2];
#pragma unroll
    for (int p = 0; p < 2; ++p) {
        int row = bm0 + rA[p];
        axr[p] = (row < Ntok)
            ? *reinterpret_cast<const float4*>(X + (size_t)row * D_MODEL + cA[p])
            : make_float4(0.f, 0.f, 0.f, 0.f);
        bwr[p] = *reinterpret_cast<const float4*>(W + (size_t)rA[p] * D_MODEL + cA[p]);
    }

    // stage chunk 0 into buf 0
    {
        char* AH = sraw;
        char* AL = sraw + TILEB;
        char* BH = sraw + 2 * TILEB;
        char* BL = sraw + 3 * TILEB;
#pragma unroll
        for (int p = 0; p < 2; ++p) {
            uint32_t off = (uint32_t)(rA[p] * SAW + cA[p]) * 2;
            uint2 h, l;
            split4(axr[p], SX, h, l);
            *reinterpret_cast<uint2*>(AH + off) = h;
            *reinterpret_cast<uint2*>(AL + off) = l;
            split4(bwr[p], SW, h, l);
            *reinterpret_cast<uint2*>(BH + off) = h;
            *reinterpret_cast<uint2*>(BL + off) = l;
        }
    }
    __syncthreads();

    for (int c = 0; c < NKC; ++c) {
        const int buf = c & 1;
        if (c + 1 < NKC) {
            const int k0 = (c + 1) * KC;
#pragma unroll
            for (int p = 0; p < 2; ++p) {
                int row = bm0 + rA[p];
                axr[p] = (row < Ntok)
                    ? *reinterpret_cast<const float4*>(X + (size_t)row * D_MODEL + k0 + cA[p])
                    : make_float4(0.f, 0.f, 0.f, 0.f);
                bwr[p] = *reinterpret_cast<const float4*>(W + (size_t)rA[p] * D_MODEL + k0 + cA[p]);
            }
        }

        const uint32_t bufA = sbase + buf * BUFB;
#pragma unroll
        for (int ks = 0; ks < KC / 16; ++ks) {
            const uint32_t kb = ks * 32;   // 16 halves = 32 bytes
            // ---- fragment loads: 4 A-ldmatrix + 4 B-ldmatrix ----
            uint32_t aH[2][4], aL[2][4];
#pragma unroll
            for (int mt = 0; mt < 2; ++mt) {
                uint32_t ab = bufA + (uint32_t)((wm * 32 + mt * 16) * SAW * 2) + aoff + kb;
                ldmx4(aH[mt][0], aH[mt][1], aH[mt][2], aH[mt][3], ab);
                ldmx4(aL[mt][0], aL[mt][1], aL[mt][2], aL[mt][3], ab + TILEB);
            }
            uint32_t bh[4][2], bl[4][2];
#pragma unroll
            for (int pr = 0; pr < 2; ++pr) {
                uint32_t bb = bufA + 2 * TILEB
                            + (uint32_t)((wn * 32 + pr * 16) * SAW * 2) + boff + kb;
                ldmx4(bh[pr * 2][0], bh[pr * 2][1], bh[pr * 2 + 1][0], bh[pr * 2 + 1][1], bb);
                ldmx4(bl[pr * 2][0], bl[pr * 2][1], bl[pr * 2 + 1][0], bl[pr * 2 + 1][1], bb + TILEB);
            }
            // ---- term-major MMA: 8 independent accumulators per term ----
#pragma unroll
            for (int ng = 0; ng < 4; ++ng)
#pragma unroll
                for (int mt = 0; mt < 2; ++mt)
                    mma16816(acc[mt][ng], aH[mt], bh[ng][0], bh[ng][1]);   // hi*hi
#pragma unroll
            for (int ng = 0; ng < 4; ++ng)
#pragma unroll
                for (int mt = 0; mt < 2; ++mt)
                    mma16816(acc[mt][ng], aH[mt], bl[ng][0], bl[ng][1]);   // hi*lo
#pragma unroll
            for (int ng = 0; ng < 4; ++ng)
#pragma unroll
                for (int mt = 0; mt < 2; ++mt)
                    mma16816(acc[mt][ng], aL[mt], bh[ng][0], bh[ng][1]);   // lo*hi
        }

        if (c + 1 < NKC) {
            char* db = sraw + ((c + 1) & 1) * BUFB;
            char* nAH = db;
            char* nAL = db + TILEB;
            char* nBH = db + 2 * TILEB;
            char* nBL = db + 3 * TILEB;
            __syncthreads();
#pragma unroll
            for (int p = 0; p < 2; ++p) {
                uint32_t off = (uint32_t)(rA[p] * SAW + cA[p]) * 2;
                uint2 h, l;
                split4(axr[p], SX, h, l);
                *reinterpret_cast<uint2*>(nAH + off) = h;
                *reinterpret_cast<uint2*>(nAL + off) = l;
                split4(bwr[p], SW, h, l);
                *reinterpret_cast<uint2*>(nBH + off) = h;
                *reinterpret_cast<uint2*>(nBL + off) = l;
            }
            __syncthreads();
        }
    }

    // ---- logits to smem (descaled) ----
    __syncthreads();
    float* Ls = reinterpret_cast<float*>(sraw);
    {
        const int g  = lane >> 2;
        const int t2 = (lane & 3) * 2;
#pragma unroll
        for (int mt = 0; mt < 2; ++mt) {
            int row = wm * 32 + mt * 16 + g;
#pragma unroll
            for (int ng = 0; ng < 4; ++ng) {
                int col = wn * 32 + ng * 8 + t2;
                *reinterpret_cast<float2*>(&Ls[row * LS_W + col]) =
                    make_float2(acc[mt][ng][0] * DESCALE, acc[mt][ng][1] * DESCALE);
                *reinterpret_cast<float2*>(&Ls[(row + 8) * LS_W + col]) =
                    make_float2(acc[mt][ng][2] * DESCALE, acc[mt][ng][3] * DESCALE);
            }
        }
    }
    __syncthreads();

    // ---- router epilogue: 1 warp per token ----
    for (int t = wid; t < BM; t += (NTHREADS / 32)) {
        int gt = bm0 + t;
        if (gt >= Ntok) continue;
        const float* Lr = Ls + t * LS_W;

        float v0 = Lr[lane];
        float v1 = Lr[lane + 32];
        float v2 = Lr[lane + 64];
        float v3 = Lr[lane + 96];

        float mx = fmaxf(fmaxf(v0, v1), fmaxf(v2, v3));
#pragma unroll
        for (int off = 16; off > 0; off >>= 1)
            mx = fmaxf(mx, __shfl_xor_sync(0xffffffffu, mx, off));

        float e0 = expf(v0 - mx);
        float e1 = expf(v1 - mx);
        float e2 = expf(v2 - mx);
        float e3 = expf(v3 - mx);
        float sum = e0 + e1 + e2 + e3;
#pragma unroll
        for (int off = 16; off > 0; off >>= 1)
            sum += __shfl_xor_sync(0xffffffffu, sum, off);

        float s0 = e0 / sum, s1 = e1 / sum, s2 = e2 / sum, s3 = e3 / sum;

        float bb0 = s0 + __ldg(BIAS + lane);
        float bb1 = s1 + __ldg(BIAS + lane + 32);
        float bb2 = s2 + __ldg(BIAS + lane + 64);
        float bb3 = s3 + __ldg(BIAS + lane + 96);

        float topw[TOPK];
        int   topi[TOPK];
#pragma unroll
        for (int i = 0; i < TOPK; ++i) {
            float bv = bb0; int bi = lane;
            if (bb1 > bv) { bv = bb1; bi = lane + 32; }
            if (bb2 > bv) { bv = bb2; bi = lane + 64; }
            if (bb3 > bv) { bv = bb3; bi = lane + 96; }
#pragma unroll
            for (int off = 16; off > 0; off >>= 1) {
                float ov = __shfl_xor_sync(0xffffffffu, bv, off);
                int   oi = __shfl_xor_sync(0xffffffffu, bi, off);
                if (ov > bv || (ov == bv && oi < bi)) { bv = ov; bi = oi; }
            }
            topi[i] = bi;
            int src = bi & 31, slot = bi >> 5;
            float sv = (slot == 0) ? s0 : (slot == 1) ? s1 : (slot == 2) ? s2 : s3;
            sv = __shfl_sync(0xffffffffu, sv, src);
            topw[i] = sv;
            if (lane == src) {
                if      (slot == 0) bb0 = -INFINITY;
                else if (slot == 1) bb1 = -INFINITY;
                else if (slot == 2) bb2 = -INFINITY;
                else                bb3 = -INFINITY;
            }
        }

        float n2 = 0.f;
#pragma unroll
        for (int i = 0; i < TOPK; ++i) n2 += topw[i] * topw[i];
        float nrm = sqrtf(n2);

        if (lane == 0) {
            size_t base = (size_t)gt * TOPK;
            float4 w0 = make_float4(topw[0] / nrm, topw[1] / nrm, topw[2] / nrm, topw[3] / nrm);
            float4 w1 = make_float4(topw[4] / nrm, topw[5] / nrm, topw[6] / nrm, topw[7] / nrm);
            *reinterpret_cast<float4*>(&OUTW[base])     = w0;
            *reinterpret_cast<float4*>(&OUTW[base + 4]) = w1;
            if (writeIdx) {
                float4 i0 = make_float4((float)topi[0], (float)topi[1], (float)topi[2], (float)topi[3]);
                float4 i1 = make_float4((float)topi[4], (float)topi[5], (float)topi[6], (float)topi[7]);
                *reinterpret_cast<float4*>(&OUTI[base])     = i0;
                *reinterpret_cast<float4*>(&OUTI[base + 4]) = i1;
            }
        }
    }
}

extern "C" void kernel_launch(void* const* d_in, const int* in_sizes, int n_in,
                              void* d_out, int out_size)
{
    const float* x    = (const float*)d_in[0];
    const float* w    = (const float*)d_in[1];
    const float* bias = (const float*)d_in[2];

    const int Ntok = in_sizes[0] / D_MODEL;

    float* outw = (float*)d_out;
    int writeIdx = (out_size >= 2 * Ntok * TOPK) ? 1 : 0;
    float* outi = outw + (size_t)Ntok * TOPK;

    cudaFuncSetAttribute(moe_router_kernel,
                         cudaFuncAttributeMaxDynamicSharedMemorySize, SMEM_REQ);

    int grid = (Ntok + BM - 1) / BM;
    moe_router_kernel<<<grid, NTHREADS, SMEM_REQ>>>(x, w, bias, outw, outi, writeIdx, Ntok);
}